// round 5
// baseline (speedup 1.0000x reference)
#include <cuda_runtime.h>

#define N_NODES 100000
#define D_DIM   128
#define E_EDGES 400000

typedef unsigned long long ull;

// ---------------- scratch (no allocations allowed) ----------------
__device__ unsigned char g_indAA[N_NODES];
__device__ unsigned char g_indAB[N_NODES];
__device__ unsigned char g_indBA[N_NODES];
__device__ float g_scaleA[N_NODES];
__device__ float g_scaleB[N_NODES];

// ---------------- degree-indicator / scale kernels ----------------
__global__ void k_zero_flags() {
    int n = blockIdx.x * blockDim.x + threadIdx.x;
    if (n < N_NODES) { g_indAA[n] = 0; g_indAB[n] = 0; g_indBA[n] = 0; }
}

__global__ void k_scatter(const int* __restrict__ dst_aa,
                          const int* __restrict__ dst_ab,
                          const int* __restrict__ dst_ba) {
    int i = blockIdx.x * blockDim.x + threadIdx.x;
    if (i < E_EDGES)            g_indAA[dst_aa[i]] = 1;
    else if (i < 2 * E_EDGES)   g_indAB[dst_ab[i - E_EDGES]] = 1;
    else if (i < 3 * E_EDGES)   g_indBA[dst_ba[i - 2 * E_EDGES]] = 1;
}

__global__ void k_scales() {
    int n = blockIdx.x * blockDim.x + threadIdx.x;
    if (n < N_NODES) {
        g_scaleA[n] = (1.0f + (float)g_indAA[n] + (float)g_indBA[n]) * (1.0f / 3.0f);
        g_scaleB[n] = (1.0f + (float)g_indAB[n]) * 0.5f;
    }
}

// ---------------- packed-fp32 helpers (Blackwell FFMA2) ----------------
__device__ __forceinline__ ull pack2_same(float x) {
    ull r; unsigned u = __float_as_uint(x);
    asm("mov.b64 %0, {%1, %1};" : "=l"(r) : "r"(u));
    return r;
}
__device__ __forceinline__ ull pack_pair(float x, float y) {
    ull r;
    asm("mov.b64 %0, {%1, %2};" : "=l"(r)
        : "r"(__float_as_uint(x)), "r"(__float_as_uint(y)));
    return r;
}
__device__ __forceinline__ void ffma2(ull &d, ull a, ull b) {
    asm("fma.rn.f32x2 %0, %1, %2, %0;" : "+l"(d) : "l"(a), "l"(b));
}
__device__ __forceinline__ float2 unpack2(ull v) {
    unsigned lo, hi;
    asm("mov.b64 {%0, %1}, %2;" : "=r"(lo), "=r"(hi) : "l"(v));
    return make_float2(__uint_as_float(lo), __uint_as_float(hi));
}

// ---------------- fused two-layer GEMM + scale + relu ----------------
// Y[r,:] = relu( (relu((X[r,:]@W0 + b0) * s[r]) @ W1 + b1) * s[r] )
// Tile: 128 rows x 128 cols per CTA, 256 threads, 8x8 micro-tile (f32x2 pairs).
// As: 128x128 fp32, XOR-swizzled on 16B chunks: (row,chunk) -> chunk ^ ((row>>3)&7)
// so transposed scalar reads in the k-loop are bank-conflict free.
// scale_sel: 0 -> g_scaleA, 1 -> g_scaleB (device globals; no host symbol lookup).
__global__ void __launch_bounds__(256, 1)
k_two_layer_gemm(const float* __restrict__ X,
                 const float* __restrict__ W0, const float* __restrict__ b0,
                 const float* __restrict__ W1, const float* __restrict__ b1,
                 int scale_sel,
                 float* __restrict__ Y, int nrows)
{
    extern __shared__ float smem[];
    float* As  = smem;                  // 16384 floats
    float* Bs0 = smem + 128 * 128;      // 16384 floats
    float* Bs1 = smem + 2 * 128 * 128;  // 16384 floats

    const float* __restrict__ scale = scale_sel ? g_scaleB : g_scaleA;

    const int tid = threadIdx.x;
    const int tx  = tid & 15;   // column group 0..15
    const int ty  = tid >> 4;   // row group    0..15
    const int block_row = blockIdx.x * 128;
    const int swz = ty & 7;     // == (row>>3)&7 for rows ty*8 .. ty*8+7

    // ---- load W0, W1 and the X tile (swizzled) ----
    #pragma unroll
    for (int it = 0; it < 16; ++it) {
        int idx = tid + it * 256;     // float4 index 0..4095
        int row = idx >> 5;           // 0..127
        int ch  = idx & 31;           // 16B chunk 0..31
        *(float4*)(Bs0 + row * 128 + ch * 4) = *(const float4*)(W0 + row * 128 + ch * 4);
        *(float4*)(Bs1 + row * 128 + ch * 4) = *(const float4*)(W1 + row * 128 + ch * 4);
        int grow = block_row + row;
        float4 x4 = make_float4(0.f, 0.f, 0.f, 0.f);
        if (grow < nrows) x4 = *(const float4*)(X + (size_t)grow * D_DIM + ch * 4);
        int sch = ch ^ ((row >> 3) & 7);
        *(float4*)(As + row * 128 + sch * 4) = x4;
    }
    __syncthreads();

    const float* a_base = As + (ty * 8) * 128;

    #pragma unroll 1
    for (int layer = 0; layer < 2; ++layer) {
        const float* Bs   = layer ? Bs1 : Bs0;
        const float* bias = layer ? b1  : b0;

        ull acc[8][4];
        #pragma unroll
        for (int i = 0; i < 8; ++i)
            #pragma unroll
            for (int g = 0; g < 4; ++g) acc[i][g] = 0ull;

        #pragma unroll 4
        for (int k = 0; k < 128; ++k) {
            // swizzled offset of element k within a row of As
            int kx = (((k >> 2) ^ swz) << 2) + (k & 3);
            ull a2[8];
            #pragma unroll
            for (int i = 0; i < 8; ++i) a2[i] = pack2_same(a_base[i * 128 + kx]);
            const float* bk = Bs + k * 128 + tx * 2;
            ull b2[4];
            #pragma unroll
            for (int g = 0; g < 4; ++g) b2[g] = *(const ull*)(bk + g * 32);
            #pragma unroll
            for (int i = 0; i < 8; ++i)
                #pragma unroll
                for (int g = 0; g < 4; ++g)
                    ffma2(acc[i][g], a2[i], b2[g]);
        }

        if (layer == 0) {
            __syncthreads();   // everyone done reading As before overwrite
            #pragma unroll
            for (int i = 0; i < 8; ++i) {
                int row  = ty * 8 + i;
                int grow = block_row + row;
                float s = (grow < nrows) ? scale[grow] : 0.f;
                #pragma unroll
                for (int g = 0; g < 4; ++g) {
                    int c = g * 32 + tx * 2;
                    float2 v = unpack2(acc[i][g]);
                    float lo = fmaxf((v.x + bias[c])     * s, 0.f);
                    float hi = fmaxf((v.y + bias[c + 1]) * s, 0.f);
                    int pch = (c >> 2) ^ swz;   // swizzled store back into As
                    *(ull*)(As + row * 128 + pch * 4 + (c & 3)) = pack_pair(lo, hi);
                }
            }
            __syncthreads();
        } else {
            #pragma unroll
            for (int i = 0; i < 8; ++i) {
                int grow = block_row + ty * 8 + i;
                if (grow < nrows) {
                    float s = scale[grow];
                    float* yr = Y + (size_t)grow * D_DIM;
                    #pragma unroll
                    for (int g = 0; g < 4; ++g) {
                        int c = g * 32 + tx * 2;
                        float2 v = unpack2(acc[i][g]);
                        float lo = fmaxf((v.x + bias[c])     * s, 0.f);
                        float hi = fmaxf((v.y + bias[c + 1]) * s, 0.f);
                        *(float2*)(yr + c) = make_float2(lo, hi);
                    }
                }
            }
        }
    }
}

// ---------------- launch ----------------
extern "C" void kernel_launch(void* const* d_in, const int* in_sizes, int n_in,
                              void* d_out, int out_size)
{
    // metadata order: featA, featB, src_aa, dst_aa, src_ab, dst_ab, src_ba, dst_ba,
    //                 Wl0, bl0, Wr0, br0, al0, ar0, Wl1, bl1, Wr1, br1, al1, ar1
    const float* featA  = (const float*)d_in[0];
    const float* featB  = (const float*)d_in[1];
    const int*   dst_aa = (const int*)d_in[3];
    const int*   dst_ab = (const int*)d_in[5];
    const int*   dst_ba = (const int*)d_in[7];
    const float* Wr0 = (const float*)d_in[10];  // (2, D, D)
    const float* br0 = (const float*)d_in[11];  // (2, D)
    const float* Wr1 = (const float*)d_in[16];
    const float* br1 = (const float*)d_in[17];
    float* out = (float*)d_out;                 // [2, N, D] float32

    // degree indicators -> per-row scales (identical for both layers)
    k_zero_flags<<<(N_NODES + 255) / 256, 256>>>();
    k_scatter<<<(3 * E_EDGES + 255) / 256, 256>>>(dst_aa, dst_ab, dst_ba);
    k_scales<<<(N_NODES + 255) / 256, 256>>>();

    const size_t smem = 3 * 128 * 128 * sizeof(float);  // 192 KB
    cudaFuncSetAttribute(k_two_layer_gemm,
                         cudaFuncAttributeMaxDynamicSharedMemorySize, (int)smem);

    const int grid = (N_NODES + 127) / 128;  // 782
    // type A: both layers fused; writes out[0]
    k_two_layer_gemm<<<grid, 256, smem>>>(featA, Wr0, br0, Wr1, br1,
                                          /*scale_sel=*/0, out, N_NODES);
    // type B: writes out[1]
    k_two_layer_gemm<<<grid, 256, smem>>>(featB,
                                          Wr0 + D_DIM * D_DIM, br0 + D_DIM,
                                          Wr1 + D_DIM * D_DIM, br1 + D_DIM,
                                          /*scale_sel=*/1,
                                          out + (size_t)N_NODES * D_DIM,
                                          N_NODES);
    (void)in_sizes; (void)n_in; (void)out_size;
}

// round 17
// speedup vs baseline: 1.2295x; 1.2295x over previous
#include <cuda_runtime.h>
#include <cstdint>

#define N_NODES 100000
#define D_DIM   128
#define E_EDGES 400000

typedef uint32_t u32; typedef unsigned long long ull;

// ---------------- scratch (no allocations allowed) ----------------
__device__ unsigned char g_indAA[N_NODES];
__device__ unsigned char g_indAB[N_NODES];
__device__ unsigned char g_indBA[N_NODES];
__device__ float g_scaleA[N_NODES];
__device__ float g_scaleB[N_NODES];

// ---------------- flag / scale kernels ----------------
__global__ void k_zero_flags() {
    int n = blockIdx.x * blockDim.x + threadIdx.x;
    if (n < N_NODES) { g_indAA[n] = 0; g_indAB[n] = 0; g_indBA[n] = 0; }
}
__global__ void k_scatter(const int* __restrict__ daa, const int* __restrict__ dab,
                          const int* __restrict__ dba) {
    int i = blockIdx.x * blockDim.x + threadIdx.x;
    if (i < E_EDGES)          g_indAA[daa[i]] = 1;
    else if (i < 2 * E_EDGES) g_indAB[dab[i - E_EDGES]] = 1;
    else if (i < 3 * E_EDGES) g_indBA[dba[i - 2 * E_EDGES]] = 1;
}
__global__ void k_scales() {
    int n = blockIdx.x * blockDim.x + threadIdx.x;
    if (n < N_NODES) {
        g_scaleA[n] = (1.0f + (float)g_indAA[n] + (float)g_indBA[n]) * (1.0f / 3.0f);
        g_scaleB[n] = (1.0f + (float)g_indAB[n]) * 0.5f;
    }
}

// ---------------- packed-fp32 helpers ----------------
__device__ __forceinline__ ull pack_pair(float x, float y) {
    ull r;
    asm("mov.b64 %0, {%1, %2};" : "=l"(r)
        : "r"(__float_as_uint(x)), "r"(__float_as_uint(y)));
    return r;
}
__device__ __forceinline__ void ffma2(ull &d, ull a, ull b) {
    asm("fma.rn.f32x2 %0, %1, %2, %0;" : "+l"(d) : "l"(a), "l"(b));
}
__device__ __forceinline__ float2 unpack2(ull v) {
    unsigned lo, hi;
    asm("mov.b64 {%0, %1}, %2;" : "=r"(lo), "=r"(hi) : "l"(v));
    return make_float2(__uint_as_float(lo), __uint_as_float(hi));
}

// ---------------- fused two-layer GEMM, k-paired FFMA2 ----------------
// Per CTA: 128 rows x 128 cols, 256 threads (tx 0..15 cols, ty 0..15 rows).
// Thread micro-tile: 8 rows (ty*8..+7) x 8 cols {tx*2+g*32, tx*2+1+g*32 : g<4}.
// acc[r][g][c01] is an f32x2 pair holding (even-k partial, odd-k partial);
// final value = lo + hi.
// As: 128x128 fp32, 16B-chunk XOR swizzle: chunk ch at row stored at ch^((row>>3)&7).
// Bp: k-pair interleaved ull Bp[64][128]: Bp[kp][c] = (W[2kp][c], W[2kp+1][c]).
#define SMEM_BP0 65536
#define SMEM_BP1 131072
#define SMEM_TOTAL 196608

__global__ void __launch_bounds__(256, 1)
k_gemm2(const float* __restrict__ featA, const float* __restrict__ featB,
        const float* __restrict__ Wr0, const float* __restrict__ br0,
        const float* __restrict__ Wr1, const float* __restrict__ br1,
        float* __restrict__ out, int nrows, int blocks_per_type)
{
    extern __shared__ unsigned char smem[];
    float* As = (float*)smem;

    const int type = (blockIdx.x >= blocks_per_type) ? 1 : 0;
    const int block_row = (blockIdx.x - type * blocks_per_type) * 128;
    const float* __restrict__ X  = type ? featB : featA;
    const float* __restrict__ W0 = Wr0 + type * (D_DIM * D_DIM);
    const float* __restrict__ W1 = Wr1 + type * (D_DIM * D_DIM);
    const float* __restrict__ b0 = br0 + type * D_DIM;
    const float* __restrict__ b1 = br1 + type * D_DIM;
    const float* __restrict__ scale = type ? g_scaleB : g_scaleA;
    float* __restrict__ Y = out + (size_t)type * N_NODES * D_DIM;

    const int tid = threadIdx.x;
    const int tx  = tid & 15;
    const int ty  = tid >> 4;
    const int swz = ty & 7;                 // == (row>>3)&7 for rows ty*8..+7

    // ---- stage weights into k-pair layout ----
    #pragma unroll
    for (int l = 0; l < 2; ++l) {
        const float* W = l ? W1 : W0;
        ull* Bp = (ull*)(smem + (l ? SMEM_BP1 : SMEM_BP0));
        #pragma unroll
        for (int it = 0; it < 8; ++it) {
            int task = tid + it * 256;          // 0..2047
            int kp = task >> 5;                 // 0..63
            int c4 = (task & 31) * 4;           // 0..124
            float4 w0 = *(const float4*)(W + (2 * kp)     * 128 + c4);
            float4 w1 = *(const float4*)(W + (2 * kp + 1) * 128 + c4);
            ulonglong2* dst = (ulonglong2*)(Bp + kp * 128 + c4);
            ulonglong2 p01, p23;
            p01.x = pack_pair(w0.x, w1.x); p01.y = pack_pair(w0.y, w1.y);
            p23.x = pack_pair(w0.z, w1.z); p23.y = pack_pair(w0.w, w1.w);
            dst[0] = p01; dst[1] = p23;
        }
    }
    // ---- X tile -> As (swizzled) ----
    #pragma unroll
    for (int it = 0; it < 16; ++it) {
        int idx = tid + it * 256;               // float4 index 0..4095
        int row = idx >> 5, ch = idx & 31;
        int grow = block_row + row;
        float4 x4 = make_float4(0.f, 0.f, 0.f, 0.f);
        if (grow < nrows) x4 = *(const float4*)(X + (size_t)grow * D_DIM + ch * 4);
        int sch = ch ^ ((row >> 3) & 7);
        *(float4*)((unsigned char*)As + row * 512 + sch * 16) = x4;
    }
    __syncthreads();

    // per-row scales
    float sr[8];
    #pragma unroll
    for (int r = 0; r < 8; ++r) {
        int grow = block_row + ty * 8 + r;
        sr[r] = (grow < nrows) ? scale[grow] : 0.f;
    }

    const unsigned char* a_ptr = (const unsigned char*)As + (ty * 8) * 512;

    #pragma unroll 1
    for (int layer = 0; layer < 2; ++layer) {
        const ull* Bp = (const ull*)(smem + (layer ? SMEM_BP1 : SMEM_BP0));
        const float* bias = layer ? b1 : b0;

        ull acc[8][4][2];
        #pragma unroll
        for (int r = 0; r < 8; ++r)
            #pragma unroll
            for (int g = 0; g < 4; ++g) { acc[r][g][0] = 0ull; acc[r][g][1] = 0ull; }

        #pragma unroll 2
        for (int kc = 0; kc < 32; ++kc) {
            int kx = (kc ^ swz) << 4;           // swizzled 16B-chunk byte offset
            ulonglong2 av[8];                    // av.x = (k0,k1), av.y = (k2,k3)
            #pragma unroll
            for (int r = 0; r < 8; ++r)
                av[r] = *(const ulonglong2*)(a_ptr + r * 512 + kx);
            #pragma unroll
            for (int h = 0; h < 2; ++h) {
                const ull* bk = Bp + (kc * 2 + h) * 128 + tx * 2;
                ulonglong2 bv[4];
                #pragma unroll
                for (int g = 0; g < 4; ++g)
                    bv[g] = *(const ulonglong2*)(bk + g * 32);
                #pragma unroll
                for (int r = 0; r < 8; ++r) {
                    ull ap = h ? av[r].y : av[r].x;
                    #pragma unroll
                    for (int g = 0; g < 4; ++g) {
                        ffma2(acc[r][g][0], ap, bv[g].x);
                        ffma2(acc[r][g][1], ap, bv[g].y);
                    }
                }
            }
        }

        // bias pairs for this thread's columns
        float2 bz[4];
        #pragma unroll
        for (int g = 0; g < 4; ++g)
            bz[g] = *(const float2*)(bias + tx * 2 + g * 32);

        if (layer == 0) {
            __syncthreads();   // all reads of As finished before overwrite
            #pragma unroll
            for (int r = 0; r < 8; ++r) {
                int row = ty * 8 + r;
                float s = sr[r];
                #pragma unroll
                for (int g = 0; g < 4; ++g) {
                    float2 p0 = unpack2(acc[r][g][0]);
                    float2 p1 = unpack2(acc[r][g][1]);
                    float v0 = fmaxf((p0.x + p0.y + bz[g].x) * s, 0.f);
                    float v1 = fmaxf((p1.x + p1.y + bz[g].y) * s, 0.f);
                    // write back into As, swizzled: c = tx*2+g*32
                    int sch = ((tx >> 1) + g * 8) ^ swz;
                    *(float2*)((unsigned char*)As + row * 512 + sch * 16 + (tx & 1) * 8)
                        = make_float2(v0, v1);
                }
            }
            __syncthreads();
        } else {
            #pragma unroll
            for (int r = 0; r < 8; ++r) {
                int grow = block_row + ty * 8 + r;
                if (grow < nrows) {
                    float s = sr[r];
                    float* yr = Y + (size_t)grow * D_DIM;
                    #pragma unroll
                    for (int g = 0; g < 4; ++g) {
                        float2 p0 = unpack2(acc[r][g][0]);
                        float2 p1 = unpack2(acc[r][g][1]);
                        float v0 = fmaxf((p0.x + p0.y + bz[g].x) * s, 0.f);
                        float v1 = fmaxf((p1.x + p1.y + bz[g].y) * s, 0.f);
                        *(float2*)(yr + tx * 2 + g * 32) = make_float2(v0, v1);
                    }
                }
            }
        }
    }
}

// ---------------- launch ----------------
extern "C" void kernel_launch(void* const* d_in, const int* in_sizes, int n_in,
                              void* d_out, int out_size)
{
    // metadata order: featA, featB, src_aa, dst_aa, src_ab, dst_ab, src_ba, dst_ba,
    //                 Wl0, bl0, Wr0, br0, al0, ar0, Wl1, bl1, Wr1, br1, al1, ar1
    const float* featA  = (const float*)d_in[0];
    const float* featB  = (const float*)d_in[1];
    const int*   dst_aa = (const int*)d_in[3];
    const int*   dst_ab = (const int*)d_in[5];
    const int*   dst_ba = (const int*)d_in[7];
    const float* Wr0 = (const float*)d_in[10];  // (2, D, D)
    const float* br0 = (const float*)d_in[11];  // (2, D)
    const float* Wr1 = (const float*)d_in[16];
    const float* br1 = (const float*)d_in[17];
    float* out = (float*)d_out;                 // [2, N, D] float32

    k_zero_flags<<<(N_NODES + 255) / 256, 256>>>();
    k_scatter<<<(3 * E_EDGES + 255) / 256, 256>>>(dst_aa, dst_ab, dst_ba);
    k_scales<<<(N_NODES + 255) / 256, 256>>>();

    cudaFuncSetAttribute(k_gemm2,
                         cudaFuncAttributeMaxDynamicSharedMemorySize, SMEM_TOTAL);

    const int bpt = (N_NODES + 127) / 128;      // 782 blocks per type
    k_gemm2<<<2 * bpt, 256, SMEM_TOTAL>>>(featA, featB, Wr0, br0, Wr1, br1,
                                          out, N_NODES, bpt);
    (void)in_sizes; (void)n_in; (void)out_size;
}